// round 13
// baseline (speedup 1.0000x reference)
#include <cuda_runtime.h>

#define E 8
#define DDIM 1024
#define NW 7                      // warps per block
#define TPB (NW * 32)             // 224
#define GRID 148
#define CFLOAT 64                 // floats per token per chunk
#define CSLOT (CFLOAT / 4)        // 16 float4 slots
#define NCH (DDIM / CFLOAT)       // 16 chunks
#define STG 4                     // warp-private pipeline stages (3 in flight)
#define WBUF (32 * CFLOAT)        // floats per stage per warp (2048)
#define SMEM_FLOATS (NW * STG * WBUF)
#define SMEM_BYTES (SMEM_FLOATS * 4)   // 224KB x rings (W now via L1)

// Global accumulators. Zero-initialized at module load; the LAST block resets
// them after consuming, so every launch / graph replay sees zeros on entry.
__device__ float g_prob_sum[E];
__device__ float g_ent_sum;
__device__ unsigned g_cnt[E];
__device__ unsigned g_done;

// Warp-private chunk stage: each lane copies part of the 32 rows THIS warp's
// lanes will read. Completion: per-thread wait_group + __syncwarp (no BAR).
__device__ __forceinline__ void warp_issue(const float* __restrict__ x, float* wbuf,
                                           int tok0, int c, int lane, int N) {
    float* buf = wbuf + (c & (STG - 1)) * WBUF;
#pragma unroll
    for (int k = 0; k < 16; ++k) {
        int i = lane + k * 32;
        int r = i >> 4;                         // row 0..31
        int s = i & 15;                         // float4 slot 0..15
        int gt = tok0 + r; if (gt > N - 1) gt = N - 1;
        const float* src = x + (size_t)gt * DDIM + c * CFLOAT + s * 4;
        float* dst = buf + r * CFLOAT + ((s ^ (r & 15)) << 2);
        unsigned d = (unsigned)__cvta_generic_to_shared(dst);
        asm volatile("cp.async.cg.shared.global [%0], [%1], 16;\n" :: "r"(d), "l"(src));
    }
    asm volatile("cp.async.commit_group;\n");
}

__global__ __launch_bounds__(TPB, 1)
void router_main(const float* __restrict__ x, const float* __restrict__ Wg,
                 const int* __restrict__ pk, float* __restrict__ out,
                 int N, int tok_per_blk) {
    extern __shared__ float sx[];                  // [NW][STG][32][CFLOAT]
    __shared__ float sh_psum[E];
    __shared__ unsigned sh_cnt[E];
    __shared__ float sh_ent;

    int tid = threadIdx.x;
    int wid = tid >> 5;
    int lane = tid & 31;
    int tok0 = blockIdx.x * tok_per_blk + wid * 32;
    float* wbuf = sx + wid * (STG * WBUF);

    // Start HBM traffic immediately: 3 chunks in flight (warp-private ring)
    warp_issue(x, wbuf, tok0, 0, lane, N);
    warp_issue(x, wbuf, tok0, 1, lane, N);
    warp_issue(x, wbuf, tok0, 2, lane, N);

    if (tid < E) { sh_psum[tid] = 0.f; sh_cnt[tid] = 0u; }
    if (tid == 0) sh_ent = 0.f;
    __syncthreads();

    int token = tok0 + lane;
    bool valid = (wid * 32 + lane < tok_per_blk) && (token < N);

    // W read through L1 (__ldg, uniform address -> 1 line/warp-LDG). Off the
    // smem crossbar, and not fenced by __syncwarp -> free scheduling across
    // chunk boundaries. 32KB stays L1-resident (60KB L1D available).
    const float4* __restrict__ w4 = (const float4*)Wg;
    int swz = lane & 15;

    // Each acc[e] chain is a STRICT ascending-d scalar fmaf sequence —
    // bit-identical to the passing kernels (one flipped top-k index fails).
    float acc[E];
#pragma unroll
    for (int e = 0; e < E; ++e) acc[e] = 0.f;

    for (int c = 0; c < NCH; ++c) {
        if (c < NCH - 2)       asm volatile("cp.async.wait_group 2;\n" ::: "memory");
        else if (c == NCH - 2) asm volatile("cp.async.wait_group 1;\n" ::: "memory");
        else                   asm volatile("cp.async.wait_group 0;\n" ::: "memory");
        __syncwarp();

        // Refill early: buffer (c+3)&3 was consumed at chunk c-1.
        if (c + 3 < NCH) warp_issue(x, wbuf, tok0, c + 3, lane, N);

        const float4* xrow = (const float4*)(wbuf + (c & (STG - 1)) * WBUF + lane * CFLOAT);
#pragma unroll
        for (int j = 0; j < CSLOT; ++j) {
            float4 xv = xrow[j ^ swz];
            float4 wv[E];
#pragma unroll
            for (int e = 0; e < E; ++e)
                wv[e] = __ldg(&w4[e * (DDIM / 4) + c * CSLOT + j]);  // uniform, L1-hit
#pragma unroll
            for (int e = 0; e < E; ++e) acc[e] = fmaf(xv.x, wv[e].x, acc[e]);
#pragma unroll
            for (int e = 0; e < E; ++e) acc[e] = fmaf(xv.y, wv[e].y, acc[e]);
#pragma unroll
            for (int e = 0; e < E; ++e) acc[e] = fmaf(xv.z, wv[e].z, acc[e]);
#pragma unroll
            for (int e = 0; e < E; ++e) acc[e] = fmaf(xv.w, wv[e].w, acc[e]);
        }
    }

    // ---- epilogue: softmax / top-k / stats, all in registers ----
    int kk = *pk; kk = kk < 1 ? 1 : (kk > E ? E : kk);
    float* out_dw  = out;
    float* out_idx = out + (size_t)N * kk;
    float* out_lg  = out + (size_t)2 * N * kk;

    if (valid) {
        float4* lp = (float4*)(out_lg + (size_t)token * E);
        lp[0] = make_float4(acc[0], acc[1], acc[2], acc[3]);
        lp[1] = make_float4(acc[4], acc[5], acc[6], acc[7]);
    }

    float m = acc[0];
#pragma unroll
    for (int e = 1; e < E; ++e) m = fmaxf(m, acc[e]);
    float p[E], s = 0.f;
#pragma unroll
    for (int e = 0; e < E; ++e) { p[e] = __expf(acc[e] - m); s += p[e]; }
    float inv = 1.f / s;
    float logs = __logf(s);
    float ent = 0.f;
#pragma unroll
    for (int e = 0; e < E; ++e) ent -= (p[e] * inv) * (acc[e] - m - logs);

    // top-k (values descending, ties -> lower index, matching lax.top_k)
    unsigned selmask = 0;
    float tmp[E];
#pragma unroll
    for (int e = 0; e < E; ++e) tmp[e] = p[e];
#pragma unroll
    for (int r = 0; r < E; ++r) {
        if (r < kk) {
            int bi = 0; float bv = tmp[0];
#pragma unroll
            for (int e = 1; e < E; ++e) { if (tmp[e] > bv) { bv = tmp[e]; bi = e; } }
            if (valid) {
                out_dw [(size_t)token * kk + r] = bv * inv;
                out_idx[(size_t)token * kk + r] = (float)bi;
            }
            selmask |= (1u << bi);
#pragma unroll
            for (int e = 0; e < E; ++e) if (e == bi) tmp[e] = -1.f;
        }
    }

    if (!valid) { ent = 0.f; selmask = 0u; inv = 0.f; }

    // Warp reduction -> shared atomics -> one global atomic set per block
    float entw = ent;
#pragma unroll
    for (int o = 16; o > 0; o >>= 1) entw += __shfl_xor_sync(0xffffffffu, entw, o);
    float psum[E];
#pragma unroll
    for (int e = 0; e < E; ++e) {
        float v = p[e] * inv;
#pragma unroll
        for (int o = 16; o > 0; o >>= 1) v += __shfl_xor_sync(0xffffffffu, v, o);
        psum[e] = v;
    }
    bool lane0 = (lane == 0);
    if (lane0) atomicAdd(&sh_ent, entw);
#pragma unroll
    for (int e = 0; e < E; ++e) {
        unsigned b = __ballot_sync(0xffffffffu, (selmask >> e) & 1u);
        if (lane0) {
            atomicAdd(&sh_cnt[e], (unsigned)__popc(b));
            atomicAdd(&sh_psum[e], psum[e]);
        }
    }
    __syncthreads();
    if (tid < E) {
        atomicAdd(&g_cnt[tid], sh_cnt[tid]);
        atomicAdd(&g_prob_sum[tid], sh_psum[tid]);
    }
    if (tid == E) atomicAdd(&g_ent_sum, sh_ent);

    // ---- last-block-done finalize (fused; single launch) ----
    __threadfence();
    __shared__ unsigned sh_last;
    if (tid == 0) sh_last = atomicAdd(&g_done, 1u);
    __syncthreads();
    if (sh_last != gridDim.x - 1u) return;

    if (tid == 0) {
        float* base = out + (size_t)2 * N * kk + (size_t)N * E;
        long long total_cap = (long long)((double)N * (double)kk * 1.25);
        long long per_cap = total_cap / E; if (per_cap < 1) per_cap = 1;
        float invN = 1.f / (float)N;
        float lb = 0.f; int nd = 0;
        for (int e = 0; e < E; ++e) {
            float cnt = (float)g_cnt[e];
            float usage = cnt * invN;
            float avg = g_prob_sum[e] * invN;
            lb += usage * avg;
            if ((long long)g_cnt[e] > per_cap) nd++;
            base[3 + e] = usage;
        }
        base[0] = lb * (float)E;
        float entm = g_ent_sum * invN;
        float rel = logf((float)E) - entm;
        base[1] = rel > 0.f ? rel : 0.f;
        base[2] = (float)nd;

        // Reset accumulators for the next launch / graph replay.
        for (int e = 0; e < E; ++e) { g_cnt[e] = 0u; g_prob_sum[e] = 0.f; }
        g_ent_sum = 0.f;
        g_done = 0u;
    }
}

extern "C" void kernel_launch(void* const* d_in, const int* in_sizes, int n_in,
                              void* d_out, int out_size) {
    const float* x = (const float*)d_in[0];
    const float* W = (const float*)d_in[1];
    const int*  pk = (const int*)d_in[2];
    int N = in_sizes[0] / DDIM;
    float* out = (float*)d_out;

    int grid = GRID;
    int tok_per_blk = (N + grid - 1) / grid;       // 222 for N=32768
    if (tok_per_blk > TPB) {                        // safety for other shapes
        grid = (N + TPB - 1) / TPB;
        tok_per_blk = TPB;
    }
    cudaFuncSetAttribute(router_main, cudaFuncAttributeMaxDynamicSharedMemorySize, SMEM_BYTES);
    router_main<<<grid, TPB, SMEM_BYTES>>>(x, W, pk, out, N, tok_per_blk);
}

// round 16
// speedup vs baseline: 1.4139x; 1.4139x over previous
#include <cuda_runtime.h>
#include <cuda.h>

#define E 8
#define DDIM 1024
#define GRID 148

// Global accumulators. Zero-initialized at module load; the LAST block resets
// them after consuming, so every launch / graph replay sees zeros on entry.
__device__ float g_prob_sum[E];
__device__ float g_ent_sum;
__device__ unsigned g_cnt[E];
__device__ unsigned g_done;

// ---------------------------------------------------------------------------
// Shared epilogue: softmax / top-k / stats / fused finalize.
// Per-token logits arrive in acc[E]; chains were strictly ascending-d fmaf.
// ---------------------------------------------------------------------------
__device__ __forceinline__ void epilogue(float* acc, bool valid, int token,
                                         int kk, float* out, int N,
                                         float* sh_psum, unsigned* sh_cnt,
                                         float* sh_ent, int tid, int lane,
                                         int grid_blocks) {
    float* out_dw  = out;
    float* out_idx = out + (size_t)N * kk;
    float* out_lg  = out + (size_t)2 * N * kk;

    if (valid) {
        float4* lp = (float4*)(out_lg + (size_t)token * E);
        lp[0] = make_float4(acc[0], acc[1], acc[2], acc[3]);
        lp[1] = make_float4(acc[4], acc[5], acc[6], acc[7]);
    }

    float m = acc[0];
#pragma unroll
    for (int e = 1; e < E; ++e) m = fmaxf(m, acc[e]);
    float p[E], s = 0.f;
#pragma unroll
    for (int e = 0; e < E; ++e) { p[e] = __expf(acc[e] - m); s += p[e]; }
    float inv = 1.f / s;
    float logs = __logf(s);
    float ent = 0.f;
#pragma unroll
    for (int e = 0; e < E; ++e) ent -= (p[e] * inv) * (acc[e] - m - logs);

    unsigned selmask = 0;
    float tmp[E];
#pragma unroll
    for (int e = 0; e < E; ++e) tmp[e] = p[e];
#pragma unroll
    for (int r = 0; r < E; ++r) {
        if (r < kk) {
            int bi = 0; float bv = tmp[0];
#pragma unroll
            for (int e = 1; e < E; ++e) { if (tmp[e] > bv) { bv = tmp[e]; bi = e; } }
            if (valid) {
                out_dw [(size_t)token * kk + r] = bv * inv;
                out_idx[(size_t)token * kk + r] = (float)bi;
            }
            selmask |= (1u << bi);
#pragma unroll
            for (int e = 0; e < E; ++e) if (e == bi) tmp[e] = -1.f;
        }
    }

    if (!valid) { ent = 0.f; selmask = 0u; inv = 0.f; }

    float entw = ent;
#pragma unroll
    for (int o = 16; o > 0; o >>= 1) entw += __shfl_xor_sync(0xffffffffu, entw, o);
    float psum[E];
#pragma unroll
    for (int e = 0; e < E; ++e) {
        float v = valid ? p[e] * inv : 0.f;
#pragma unroll
        for (int o = 16; o > 0; o >>= 1) v += __shfl_xor_sync(0xffffffffu, v, o);
        psum[e] = v;
    }
    bool lane0 = (lane == 0);
    if (lane0) atomicAdd(sh_ent, entw);
#pragma unroll
    for (int e = 0; e < E; ++e) {
        unsigned b = __ballot_sync(0xffffffffu, (selmask >> e) & 1u);
        if (lane0) {
            atomicAdd(&sh_cnt[e], (unsigned)__popc(b));
            atomicAdd(&sh_psum[e], psum[e]);
        }
    }
    __syncthreads();
    if (tid < E) {
        atomicAdd(&g_cnt[tid], sh_cnt[tid]);
        atomicAdd(&g_prob_sum[tid], sh_psum[tid]);
    }
    if (tid == E) atomicAdd(&g_ent_sum, *sh_ent);

    __threadfence();
    __shared__ unsigned sh_last;
    if (tid == 0) sh_last = atomicAdd(&g_done, 1u);
    __syncthreads();
    if (sh_last != (unsigned)(grid_blocks - 1)) return;

    if (tid == 0) {
        float* base = out + (size_t)2 * N * kk + (size_t)N * E;
        long long total_cap = (long long)((double)N * (double)kk * 1.25);
        long long per_cap = total_cap / E; if (per_cap < 1) per_cap = 1;
        float invN = 1.f / (float)N;
        float lb = 0.f; int nd = 0;
        for (int e = 0; e < E; ++e) {
            float cnt = (float)g_cnt[e];
            float usage = cnt * invN;
            float avg = g_prob_sum[e] * invN;
            lb += usage * avg;
            if ((long long)g_cnt[e] > per_cap) nd++;
            base[3 + e] = usage;
        }
        base[0] = lb * (float)E;
        float entm = g_ent_sum * invN;
        float rel = logf((float)E) - entm;
        base[1] = rel > 0.f ? rel : 0.f;
        base[2] = (float)nd;

        for (int e = 0; e < E; ++e) { g_cnt[e] = 0u; g_prob_sum[e] = 0.f; }
        g_ent_sum = 0.f;
        g_done = 0u;
    }
}

// ===========================================================================
// Path A: TMA warp-specialized (preferred)
// ===========================================================================
#define NCW 7
#define TPB_T 256
#define ROWS 224
#define CF_T 32
#define CS_T (CF_T / 4)
#define NCH_T (DDIM / CF_T)        // 32
#define STG_T 5
#define STAGE_BYTES (ROWS * CF_T * 4)              // 28672
#define W_BYTES (E * DDIM * 4)                     // 32768
#define SMEM_T (W_BYTES + STG_T * STAGE_BYTES)     // 176128

__device__ __forceinline__ unsigned smem_u32(const void* p) {
    unsigned a;
    asm("{ .reg .u64 t; cvta.to.shared.u64 t, %1; cvt.u32.u64 %0, t; }"
        : "=r"(a) : "l"(p));
    return a;
}
__device__ __forceinline__ void mbar_init(unsigned addr, unsigned cnt) {
    asm volatile("mbarrier.init.shared.b64 [%0], %1;" :: "r"(addr), "r"(cnt) : "memory");
}
__device__ __forceinline__ void fence_proxy_async_cta() {
    asm volatile("fence.proxy.async.shared::cta;" ::: "memory");
}
__device__ __forceinline__ void mbar_arrive(unsigned addr) {
    asm volatile("mbarrier.arrive.shared.b64 _, [%0];" :: "r"(addr) : "memory");
}
__device__ __forceinline__ void mbar_expect_tx(unsigned addr, unsigned bytes) {
    asm volatile("mbarrier.arrive.expect_tx.shared.b64 _, [%0], %1;"
                 :: "r"(addr), "r"(bytes) : "memory");
}
// Bounded wait: in the working pipeline this exits after 1-2 polls. If the
// barrier never flips (pipeline bug), it gives up after ~2^18 polls so the
// kernel terminates with wrong data instead of hanging the container.
__device__ __forceinline__ void mbar_wait(unsigned addr, unsigned parity) {
    unsigned done;
    asm volatile(
        "{\n\t.reg .pred P;\n\t.reg .u32 n;\n\t"
        "mov.u32 n, 0;\n"
        "W_%=:\n\t"
        "mbarrier.try_wait.parity.acquire.cta.shared::cta.b64 P, [%1], %2, 0x3E8;\n\t"
        "@P bra D_%=;\n\t"
        "add.u32 n, n, 1;\n\t"
        "setp.lt.u32 P, n, 262144;\n\t"
        "@P bra W_%=;\n"
        "D_%=:\n\t"
        "mov.u32 %0, n;\n\t}"
        : "=r"(done) : "r"(addr), "r"(parity) : "memory");
}
__device__ __forceinline__ void tma_load_2d(unsigned dst, const CUtensorMap* map,
                                            int cx, int cy, unsigned mbar) {
    asm volatile(
        "cp.async.bulk.tensor.2d.shared::cta.global.tile.mbarrier::complete_tx::bytes "
        "[%0], [%1, {%2, %3}], [%4];"
        :: "r"(dst), "l"(map), "r"(cx), "r"(cy), "r"(mbar) : "memory");
}

__global__ __launch_bounds__(TPB_T, 1)
void router_tma(const __grid_constant__ CUtensorMap tmap,
                const float* __restrict__ Wg,
                const int* __restrict__ pk, float* __restrict__ out,
                int N, int tok_per_blk) {
    extern __shared__ __align__(1024) float smem[];
    float* sW = smem;
    char*  sx = (char*)smem + W_BYTES;
    __shared__ unsigned long long mb_full[STG_T];
    __shared__ unsigned long long mb_empty[STG_T];
    __shared__ float sh_psum[E];
    __shared__ unsigned sh_cnt[E];
    __shared__ float sh_ent;

    int tid = threadIdx.x;
    int wid = tid >> 5;
    int lane = tid & 31;
    int row0 = blockIdx.x * tok_per_blk;

    if (tid == 0) {
#pragma unroll
        for (int s = 0; s < STG_T; ++s) {
            mbar_init(smem_u32(&mb_full[s]), 1);
            mbar_init(smem_u32(&mb_empty[s]), NCW);
        }
        // CRITICAL: make generic-proxy mbarrier.init visible to the async
        // proxy (TMA engine) before any cp.async.bulk.tensor uses the barrier.
        fence_proxy_async_cta();
    }
    for (int i = tid; i < (E * DDIM) / 4; i += TPB_T)
        ((float4*)sW)[i] = ((const float4*)Wg)[i];
    if (tid < E) { sh_psum[tid] = 0.f; sh_cnt[tid] = 0u; }
    if (tid == 0) sh_ent = 0.f;
    __syncthreads();

    int rowi = wid * 32 + lane;
    int token = row0 + rowi;
    bool valid = (wid < NCW) && (rowi < tok_per_blk) && (token < N);

    float acc[E];
#pragma unroll
    for (int e = 0; e < E; ++e) acc[e] = 0.f;

    if (wid == NCW) {
        // ---- producer warp: one elected thread drives the TMA pipeline ----
        if (lane == 0) {
            for (int c = 0; c < NCH_T; ++c) {
                int s = c % STG_T, k = c / STG_T;
                if (k > 0) mbar_wait(smem_u32(&mb_empty[s]), (unsigned)((k - 1) & 1));
                unsigned fb = smem_u32(&mb_full[s]);
                mbar_expect_tx(fb, STAGE_BYTES);
                tma_load_2d(smem_u32(sx + s * STAGE_BYTES), &tmap, c * CF_T, row0, fb);
            }
        }
    } else {
        // ---- consumer warps: pure LDS+FFMA stream, zero fill instructions ----
        const float4* __restrict__ w4 = (const float4*)sW;
        int swz = rowi & 7;
        const char* myrow = sx + rowi * (CF_T * 4);

        for (int c = 0; c < NCH_T; ++c) {
            int s = c % STG_T;
            mbar_wait(smem_u32(&mb_full[s]), (unsigned)((c / STG_T) & 1));

            const float4* xrow = (const float4*)(myrow + s * STAGE_BYTES);
#pragma unroll
            for (int j = 0; j < CS_T; ++j) {
                float4 xv = xrow[j ^ swz];          // TMA SW128 swizzle
                float4 wv[E];
#pragma unroll
                for (int e = 0; e < E; ++e)
                    wv[e] = w4[e * (DDIM / 4) + c * CS_T + j];  // uniform broadcast
                // Each acc[e] chain: STRICT ascending-d scalar fmaf sequence —
                // bit-identical to the passing kernels (interleaved by
                // component only; per-chain rounding untouched).
#pragma unroll
                for (int e = 0; e < E; ++e) acc[e] = fmaf(xv.x, wv[e].x, acc[e]);
#pragma unroll
                for (int e = 0; e < E; ++e) acc[e] = fmaf(xv.y, wv[e].y, acc[e]);
#pragma unroll
                for (int e = 0; e < E; ++e) acc[e] = fmaf(xv.z, wv[e].z, acc[e]);
#pragma unroll
                for (int e = 0; e < E; ++e) acc[e] = fmaf(xv.w, wv[e].w, acc[e]);
            }
            __syncwarp();
            if (lane == 0) mbar_arrive(smem_u32(&mb_empty[s]));
        }
    }

    int kk = *pk; kk = kk < 1 ? 1 : (kk > E ? E : kk);
    epilogue(acc, valid, token, kk, out, N, sh_psum, sh_cnt, &sh_ent,
             tid, lane, gridDim.x);
}

// ===========================================================================
// Path B: proven cp.async warp-ring kernel (round-11, 45.5us) as fallback
// ===========================================================================
#define NW_C 7
#define TPB_C (NW_C * 32)
#define CF_C 64
#define CS_C (CF_C / 4)
#define NCH_C (DDIM / CF_C)
#define STG_C 3
#define WBUF_C (32 * CF_C)
#define SMEM_C ((E * DDIM + NW_C * STG_C * WBUF_C) * 4)

__device__ __forceinline__ void warp_issue(const float* __restrict__ x, float* wbuf,
                                           int tok0, int c, int lane, int N) {
    float* buf = wbuf + (c % STG_C) * WBUF_C;
#pragma unroll
    for (int k = 0; k < 16; ++k) {
        int i = lane + k * 32;
        int r = i >> 4;
        int s = i & 15;
        int gt = tok0 + r; if (gt > N - 1) gt = N - 1;
        const float* src = x + (size_t)gt * DDIM + c * CF_C + s * 4;
        float* dst = buf + r * CF_C + ((s ^ (r & 15)) << 2);
        unsigned d = (unsigned)__cvta_generic_to_shared(dst);
        asm volatile("cp.async.cg.shared.global [%0], [%1], 16;\n" :: "r"(d), "l"(src));
    }
    asm volatile("cp.async.commit_group;\n");
}

__global__ __launch_bounds__(TPB_C, 1)
void router_cp(const float* __restrict__ x, const float* __restrict__ Wg,
               const int* __restrict__ pk, float* __restrict__ out,
               int N, int tok_per_blk) {
    extern __shared__ float smem[];
    float* sW = smem;
    float* sx = smem + E * DDIM;
    __shared__ float sh_psum[E];
    __shared__ unsigned sh_cnt[E];
    __shared__ float sh_ent;

    int tid = threadIdx.x;
    int wid = tid >> 5;
    int lane = tid & 31;
    int tok0 = blockIdx.x * tok_per_blk + wid * 32;
    float* wbuf = sx + wid * (STG_C * WBUF_C);

    warp_issue(x, wbuf, tok0, 0, lane, N);
    warp_issue(x, wbuf, tok0, 1, lane, N);

    for (int i = tid; i < (E * DDIM) / 4; i += TPB_C)
        ((float4*)sW)[i] = ((const float4*)Wg)[i];
    if (tid < E) { sh_psum[tid] = 0.f; sh_cnt[tid] = 0u; }
    if (tid == 0) sh_ent = 0.f;
    __syncthreads();

    int token = tok0 + lane;
    bool valid = (wid * 32 + lane < tok_per_blk) && (token < N);

    const float4* __restrict__ w4 = (const float4*)sW;
    int swz = lane & 15;

    float acc[E];
#pragma unroll
    for (int e = 0; e < E; ++e) acc[e] = 0.f;

    for (int c = 0; c < NCH_C; ++c) {
        if (c < NCH_C - 1) asm volatile("cp.async.wait_group 1;\n" ::: "memory");
        else               asm volatile("cp.async.wait_group 0;\n" ::: "memory");
        __syncwarp();

        const float4* xrow = (const float4*)(wbuf + (c % STG_C) * WBUF_C + lane * CF_C);
#pragma unroll
        for (int j = 0; j < CS_C; ++j) {
            float4 xv = xrow[j ^ swz];
            float4 wv[E];
#pragma unroll
            for (int e = 0; e < E; ++e)
                wv[e] = w4[e * (DDIM / 4) + c * CS_C + j];
#pragma unroll
            for (int e = 0; e < E; ++e) acc[e] = fmaf(xv.x, wv[e].x, acc[e]);
#pragma unroll
            for (int e = 0; e < E; ++e) acc[e] = fmaf(xv.y, wv[e].y, acc[e]);
#pragma unroll
            for (int e = 0; e < E; ++e) acc[e] = fmaf(xv.z, wv[e].z, acc[e]);
#pragma unroll
            for (int e = 0; e < E; ++e) acc[e] = fmaf(xv.w, wv[e].w, acc[e]);
        }
        if (c + 2 < NCH_C) warp_issue(x, wbuf, tok0, c + 2, lane, N);
    }

    int kk = *pk; kk = kk < 1 ? 1 : (kk > E ? E : kk);
    epilogue(acc, valid, token, kk, out, N, sh_psum, sh_cnt, &sh_ent,
             tid, lane, gridDim.x);
}

// ===========================================================================
// Host (no statics: everything recomputed per call; deterministic)
// ===========================================================================
typedef CUresult (*EncodeTiledFn)(
    CUtensorMap*, CUtensorMapDataType, cuuint32_t, void*,
    const cuuint64_t*, const cuuint64_t*, const cuuint32_t*, const cuuint32_t*,
    CUtensorMapInterleave, CUtensorMapSwizzle, CUtensorMapL2promotion,
    CUtensorMapFloatOOBfill);

extern "C" void kernel_launch(void* const* d_in, const int* in_sizes, int n_in,
                              void* d_out, int out_size) {
    const float* x = (const float*)d_in[0];
    const float* W = (const float*)d_in[1];
    const int*  pk = (const int*)d_in[2];
    int N = in_sizes[0] / DDIM;
    float* out = (float*)d_out;

    int grid = GRID;
    int tok_per_blk = (N + grid - 1) / grid;
    bool shape_ok = tok_per_blk <= ROWS;
    if (!shape_ok) {
        grid = (N + TPB_C - 1) / TPB_C;
        tok_per_blk = TPB_C;
    }

    // Resolve driver entry point (per call; no statics allowed).
    EncodeTiledFn enc = nullptr;
    {
        void* p = nullptr;
#if CUDART_VERSION >= 12050
        cudaDriverEntryPointQueryResult st;
        if (cudaGetDriverEntryPointByVersion("cuTensorMapEncodeTiled", &p, 12000,
                                             cudaEnableDefault, &st) == cudaSuccess &&
            st == cudaDriverEntryPointSuccess)
            enc = (EncodeTiledFn)p;
#else
        if (cudaGetDriverEntryPoint("cuTensorMapEncodeTiled", &p,
                                    cudaEnableDefault) == cudaSuccess)
            enc = (EncodeTiledFn)p;
#endif
    }

    bool use_tma = false;
    CUtensorMap tmap;
    if (shape_ok && enc) {
        cuuint64_t dims[2]    = {(cuuint64_t)DDIM, (cuuint64_t)N};
        cuuint64_t strides[1] = {(cuuint64_t)DDIM * sizeof(float)};
        cuuint32_t box[2]     = {CF_T, ROWS};
        cuuint32_t estr[2]    = {1, 1};
        if (enc(&tmap, CU_TENSOR_MAP_DATA_TYPE_FLOAT32, 2, (void*)x,
                dims, strides, box, estr,
                CU_TENSOR_MAP_INTERLEAVE_NONE, CU_TENSOR_MAP_SWIZZLE_128B,
                CU_TENSOR_MAP_L2_PROMOTION_L2_128B,
                CU_TENSOR_MAP_FLOAT_OOB_FILL_NONE) == CUDA_SUCCESS)
            use_tma = true;
    }

    if (use_tma) {
        cudaFuncSetAttribute(router_tma,
                             cudaFuncAttributeMaxDynamicSharedMemorySize, SMEM_T);
        router_tma<<<grid, TPB_T, SMEM_T>>>(tmap, W, pk, out, N, tok_per_blk);
    } else {
        cudaFuncSetAttribute(router_cp,
                             cudaFuncAttributeMaxDynamicSharedMemorySize, SMEM_C);
        router_cp<<<grid, TPB_C, SMEM_C>>>(x, W, pk, out, N, tok_per_blk);
    }
}

// round 17
// speedup vs baseline: 1.5109x; 1.0686x over previous
#include <cuda_runtime.h>
#include <cuda.h>

#define E 8
#define DDIM 1024
#define GRID 148

__device__ float g_prob_sum[E];
__device__ float g_ent_sum;
__device__ unsigned g_cnt[E];
__device__ unsigned g_done;

// ---------------------------------------------------------------------------
// Shared epilogue: softmax / top-k / stats / fused finalize.
// ---------------------------------------------------------------------------
__device__ __forceinline__ void epilogue(float* acc, bool valid, int token,
                                         int kk, float* out, int N,
                                         float* sh_psum, unsigned* sh_cnt,
                                         float* sh_ent, int tid, int lane,
                                         int grid_blocks) {
    float* out_dw  = out;
    float* out_idx = out + (size_t)N * kk;
    float* out_lg  = out + (size_t)2 * N * kk;

    if (valid) {
        float4* lp = (float4*)(out_lg + (size_t)token * E);
        lp[0] = make_float4(acc[0], acc[1], acc[2], acc[3]);
        lp[1] = make_float4(acc[4], acc[5], acc[6], acc[7]);
    }

    float m = acc[0];
#pragma unroll
    for (int e = 1; e < E; ++e) m = fmaxf(m, acc[e]);
    float p[E], s = 0.f;
#pragma unroll
    for (int e = 0; e < E; ++e) { p[e] = __expf(acc[e] - m); s += p[e]; }
    float inv = 1.f / s;
    float logs = __logf(s);
    float ent = 0.f;
#pragma unroll
    for (int e = 0; e < E; ++e) ent -= (p[e] * inv) * (acc[e] - m - logs);

    unsigned selmask = 0;
    float tmp[E];
#pragma unroll
    for (int e = 0; e < E; ++e) tmp[e] = p[e];
#pragma unroll
    for (int r = 0; r < E; ++r) {
        if (r < kk) {
            int bi = 0; float bv = tmp[0];
#pragma unroll
            for (int e = 1; e < E; ++e) { if (tmp[e] > bv) { bv = tmp[e]; bi = e; } }
            if (valid) {
                out_dw [(size_t)token * kk + r] = bv * inv;
                out_idx[(size_t)token * kk + r] = (float)bi;
            }
            selmask |= (1u << bi);
#pragma unroll
            for (int e = 0; e < E; ++e) if (e == bi) tmp[e] = -1.f;
        }
    }

    if (!valid) { ent = 0.f; selmask = 0u; inv = 0.f; }

    float entw = ent;
#pragma unroll
    for (int o = 16; o > 0; o >>= 1) entw += __shfl_xor_sync(0xffffffffu, entw, o);
    float psum[E];
#pragma unroll
    for (int e = 0; e < E; ++e) {
        float v = valid ? p[e] * inv : 0.f;
#pragma unroll
        for (int o = 16; o > 0; o >>= 1) v += __shfl_xor_sync(0xffffffffu, v, o);
        psum[e] = v;
    }
    bool lane0 = (lane == 0);
    if (lane0) atomicAdd(sh_ent, entw);
#pragma unroll
    for (int e = 0; e < E; ++e) {
        unsigned b = __ballot_sync(0xffffffffu, (selmask >> e) & 1u);
        if (lane0) {
            atomicAdd(&sh_cnt[e], (unsigned)__popc(b));
            atomicAdd(&sh_psum[e], psum[e]);
        }
    }
    __syncthreads();
    if (tid < E) {
        atomicAdd(&g_cnt[tid], sh_cnt[tid]);
        atomicAdd(&g_prob_sum[tid], sh_psum[tid]);
    }
    if (tid == E) atomicAdd(&g_ent_sum, *sh_ent);

    __threadfence();
    __shared__ unsigned sh_last;
    if (tid == 0) sh_last = atomicAdd(&g_done, 1u);
    __syncthreads();
    if (sh_last != (unsigned)(grid_blocks - 1)) return;

    if (tid == 0) {
        float* base = out + (size_t)2 * N * kk + (size_t)N * E;
        long long total_cap = (long long)((double)N * (double)kk * 1.25);
        long long per_cap = total_cap / E; if (per_cap < 1) per_cap = 1;
        float invN = 1.f / (float)N;
        float lb = 0.f; int nd = 0;
        for (int e = 0; e < E; ++e) {
            float cnt = (float)g_cnt[e];
            float usage = cnt * invN;
            float avg = g_prob_sum[e] * invN;
            lb += usage * avg;
            if ((long long)g_cnt[e] > per_cap) nd++;
            base[3 + e] = usage;
        }
        base[0] = lb * (float)E;
        float entm = g_ent_sum * invN;
        float rel = logf((float)E) - entm;
        base[1] = rel > 0.f ? rel : 0.f;
        base[2] = (float)nd;

        for (int e = 0; e < E; ++e) { g_cnt[e] = 0u; g_prob_sum[e] = 0.f; }
        g_ent_sum = 0.f;
        g_done = 0u;
    }
}

// ===========================================================================
// Path A: TMA warp-specialized, double-chunk stages, register-staged x
// ===========================================================================
#define NCW 7
#define TPB_T 256
#define ROWS 224
#define CF_T 32                     // floats per row per sub-tile (128 B, SW128)
#define CS_T (CF_T / 4)             // 8 float4 per sub-tile row
#define SUB_BYTES (ROWS * CF_T * 4)            // 28672
#define NST 2                       // sub-tiles (chunks) per stage
#define STAGE_BYTES (NST * SUB_BYTES)          // 57344
#define NSTG_IT (DDIM / (NST * CF_T))          // 16 stage iterations
#define STG_T 3
#define W_BYTES (E * DDIM * 4)
#define SMEM_T (W_BYTES + STG_T * STAGE_BYTES) // 204800

__device__ __forceinline__ unsigned smem_u32(const void* p) {
    unsigned a;
    asm("{ .reg .u64 t; cvta.to.shared.u64 t, %1; cvt.u32.u64 %0, t; }"
        : "=r"(a) : "l"(p));
    return a;
}
__device__ __forceinline__ void mbar_init(unsigned addr, unsigned cnt) {
    asm volatile("mbarrier.init.shared.b64 [%0], %1;" :: "r"(addr), "r"(cnt) : "memory");
}
__device__ __forceinline__ void fence_proxy_async_cta() {
    asm volatile("fence.proxy.async.shared::cta;" ::: "memory");
}
__device__ __forceinline__ void mbar_arrive(unsigned addr) {
    asm volatile("mbarrier.arrive.shared.b64 _, [%0];" :: "r"(addr) : "memory");
}
__device__ __forceinline__ void mbar_expect_tx(unsigned addr, unsigned bytes) {
    asm volatile("mbarrier.arrive.expect_tx.shared.b64 _, [%0], %1;"
                 :: "r"(addr), "r"(bytes) : "memory");
}
// Bounded wait: exits after ~2^18 polls if the pipeline wedges (wrong answer
// with diagnostics instead of a dead container); free in the working case.
__device__ __forceinline__ void mbar_wait(unsigned addr, unsigned parity) {
    unsigned done;
    asm volatile(
        "{\n\t.reg .pred P;\n\t.reg .u32 n;\n\t"
        "mov.u32 n, 0;\n"
        "W_%=:\n\t"
        "mbarrier.try_wait.parity.acquire.cta.shared::cta.b64 P, [%1], %2, 0x3E8;\n\t"
        "@P bra D_%=;\n\t"
        "add.u32 n, n, 1;\n\t"
        "setp.lt.u32 P, n, 262144;\n\t"
        "@P bra W_%=;\n"
        "D_%=:\n\t"
        "mov.u32 %0, n;\n\t}"
        : "=r"(done) : "r"(addr), "r"(parity) : "memory");
}
__device__ __forceinline__ void tma_load_2d(unsigned dst, const CUtensorMap* map,
                                            int cx, int cy, unsigned mbar) {
    asm volatile(
        "cp.async.bulk.tensor.2d.shared::cta.global.tile.mbarrier::complete_tx::bytes "
        "[%0], [%1, {%2, %3}], [%4];"
        :: "r"(dst), "l"(map), "r"(cx), "r"(cy), "r"(mbar) : "memory");
}

__global__ __launch_bounds__(TPB_T, 1)
void router_tma(const __grid_constant__ CUtensorMap tmap,
                const float* __restrict__ Wg,
                const int* __restrict__ pk, float* __restrict__ out,
                int N, int tok_per_blk) {
    extern __shared__ __align__(1024) float smem[];
    float* sW = smem;
    char*  sx = (char*)smem + W_BYTES;
    __shared__ unsigned long long mb_full[STG_T];
    __shared__ unsigned long long mb_empty[STG_T];
    __shared__ float sh_psum[E];
    __shared__ unsigned sh_cnt[E];
    __shared__ float sh_ent;

    int tid = threadIdx.x;
    int wid = tid >> 5;
    int lane = tid & 31;
    int row0 = blockIdx.x * tok_per_blk;

    if (tid == 0) {
#pragma unroll
        for (int s = 0; s < STG_T; ++s) {
            mbar_init(smem_u32(&mb_full[s]), 1);
            mbar_init(smem_u32(&mb_empty[s]), NCW);
        }
        fence_proxy_async_cta();   // order mbarrier.init before async-proxy use
    }
    for (int i = tid; i < (E * DDIM) / 4; i += TPB_T)
        ((float4*)sW)[i] = ((const float4*)Wg)[i];
    if (tid < E) { sh_psum[tid] = 0.f; sh_cnt[tid] = 0u; }
    if (tid == 0) sh_ent = 0.f;
    __syncthreads();

    int rowi = wid * 32 + lane;
    int token = row0 + rowi;
    bool valid = (wid < NCW) && (rowi < tok_per_blk) && (token < N);

    float acc[E];
#pragma unroll
    for (int e = 0; e < E; ++e) acc[e] = 0.f;

    if (wid == NCW) {
        // ---- producer: 16 stages, 2 TMA sub-tiles per stage, 1 barrier ----
        if (lane == 0) {
            for (int t = 0; t < NSTG_IT; ++t) {
                int s = t % STG_T, k = t / STG_T;
                if (k > 0) mbar_wait(smem_u32(&mb_empty[s]), (unsigned)((k - 1) & 1));
                unsigned fb = smem_u32(&mb_full[s]);
                mbar_expect_tx(fb, STAGE_BYTES);
                char* base = sx + s * STAGE_BYTES;
                tma_load_2d(smem_u32(base),             &tmap, (2*t    ) * CF_T, row0, fb);
                tma_load_2d(smem_u32(base + SUB_BYTES), &tmap, (2*t + 1) * CF_T, row0, fb);
            }
        }
    } else {
        // ---- consumers: register-stage x, release buffer early, FFMA off regs
        const float4* __restrict__ w4 = (const float4*)sW;
        int swz = rowi & 7;
        const char* myrow = sx + rowi * (CF_T * 4);

        for (int t = 0; t < NSTG_IT; ++t) {
            int s = t % STG_T;
            mbar_wait(smem_u32(&mb_full[s]), (unsigned)((t / STG_T) & 1));

            // Pull this stage's 16 float4 (both sub-tiles) into registers.
            const float4* r0 = (const float4*)(myrow + s * STAGE_BYTES);
            const float4* r1 = (const float4*)(myrow + s * STAGE_BYTES + SUB_BYTES);
            float4 xr[2 * CS_T];
#pragma unroll
            for (int j = 0; j < CS_T; ++j) xr[j]        = r0[j ^ swz];
#pragma unroll
            for (int j = 0; j < CS_T; ++j) xr[CS_T + j] = r1[j ^ swz];

            // Buffer consumed -> release to producer NOW (deeper pipeline).
            __syncwarp();
            if (lane == 0) mbar_arrive(smem_u32(&mb_empty[s]));

            // Compute both chunks purely from registers + W broadcasts.
            // Each acc[e] chain: STRICT ascending-d scalar fmaf sequence —
            // bit-identical to the passing kernels.
#pragma unroll
            for (int h = 0; h < NST; ++h) {
                int c = 2 * t + h;
#pragma unroll
                for (int j = 0; j < CS_T; ++j) {
                    float4 xv = xr[h * CS_T + j];
                    float4 wv[E];
#pragma unroll
                    for (int e = 0; e < E; ++e)
                        wv[e] = w4[e * (DDIM / 4) + c * CS_T + j];
#pragma unroll
                    for (int e = 0; e < E; ++e) acc[e] = fmaf(xv.x, wv[e].x, acc[e]);
#pragma unroll
                    for (int e = 0; e < E; ++e) acc[e] = fmaf(xv.y, wv[e].y, acc[e]);
#pragma unroll
                    for (int e = 0; e < E; ++e) acc[e] = fmaf(xv.z, wv[e].z, acc[e]);
#pragma unroll
                    for (int e = 0; e < E; ++e) acc[e] = fmaf(xv.w, wv[e].w, acc[e]);
                }
            }
        }
    }

    int kk = *pk; kk = kk < 1 ? 1 : (kk > E ? E : kk);
    epilogue(acc, valid, token, kk, out, N, sh_psum, sh_cnt, &sh_ent,
             tid, lane, gridDim.x);
}

// ===========================================================================
// Path B: proven cp.async warp-ring kernel (fallback)
// ===========================================================================
#define NW_C 7
#define TPB_C (NW_C * 32)
#define CF_C 64
#define CS_C (CF_C / 4)
#define NCH_C (DDIM / CF_C)
#define STG_C 3
#define WBUF_C (32 * CF_C)
#define SMEM_C ((E * DDIM + NW_C * STG_C * WBUF_C) * 4)

__device__ __forceinline__ void warp_issue(const float* __restrict__ x, float* wbuf,
                                           int tok0, int c, int lane, int N) {
    float* buf = wbuf + (c % STG_C) * WBUF_C;
#pragma unroll
    for (int k = 0; k < 16; ++k) {
        int i = lane + k * 32;
        int r = i >> 4;
        int s = i & 15;
        int gt = tok0 + r; if (gt > N - 1) gt = N - 1;
        const float* src = x + (size_t)gt * DDIM + c * CF_C + s * 4;
        float* dst = buf + r * CF_C + ((s ^ (r & 15)) << 2);
        unsigned d = (unsigned)__cvta_generic_to_shared(dst);
        asm volatile("cp.async.cg.shared.global [%0], [%1], 16;\n" :: "r"(d), "l"(src));
    }
    asm volatile("cp.async.commit_group;\n");
}

__global__ __launch_bounds__(TPB_C, 1)
void router_cp(const float* __restrict__ x, const float* __restrict__ Wg,
               const int* __restrict__ pk, float* __restrict__ out,
               int N, int tok_per_blk) {
    extern __shared__ float smem[];
    float* sW = smem;
    float* sx = smem + E * DDIM;
    __shared__ float sh_psum[E];
    __shared__ unsigned sh_cnt[E];
    __shared__ float sh_ent;

    int tid = threadIdx.x;
    int wid = tid >> 5;
    int lane = tid & 31;
    int tok0 = blockIdx.x * tok_per_blk + wid * 32;
    float* wbuf = sx + wid * (STG_C * WBUF_C);

    warp_issue(x, wbuf, tok0, 0, lane, N);
    warp_issue(x, wbuf, tok0, 1, lane, N);

    for (int i = tid; i < (E * DDIM) / 4; i += TPB_C)
        ((float4*)sW)[i] = ((const float4*)Wg)[i];
    if (tid < E) { sh_psum[tid] = 0.f; sh_cnt[tid] = 0u; }
    if (tid == 0) sh_ent = 0.f;
    __syncthreads();

    int token = tok0 + lane;
    bool valid = (wid * 32 + lane < tok_per_blk) && (token < N);

    const float4* __restrict__ w4 = (const float4*)sW;
    int swz = lane & 15;

    float acc[E];
#pragma unroll
    for (int e = 0; e < E; ++e) acc[e] = 0.f;

    for (int c = 0; c < NCH_C; ++c) {
        if (c < NCH_C - 1) asm volatile("cp.async.wait_group 1;\n" ::: "memory");
        else               asm volatile("cp.async.wait_group 0;\n" ::: "memory");
        __syncwarp();

        const float4* xrow = (const float4*)(wbuf + (c % STG_C) * WBUF_C + lane * CF_C);
#pragma unroll
        for (int j = 0; j < CS_C; ++j) {
            float4 xv = xrow[j ^ swz];
            float4 wv[E];
#pragma unroll
            for (int e = 0; e < E; ++e)
                wv[e] = w4[e * (DDIM / 4) + c * CS_C + j];
#pragma unroll
            for (int e = 0; e < E; ++e) acc[e] = fmaf(xv.x, wv[e].x, acc[e]);
#pragma unroll
            for (int e = 0; e < E; ++e) acc[e] = fmaf(xv.y, wv[e].y, acc[e]);
#pragma unroll
            for (int e = 0; e < E; ++e) acc[e] = fmaf(xv.z, wv[e].z, acc[e]);
#pragma unroll
            for (int e = 0; e < E; ++e) acc[e] = fmaf(xv.w, wv[e].w, acc[e]);
        }
        if (c + 2 < NCH_C) warp_issue(x, wbuf, tok0, c + 2, lane, N);
    }

    int kk = *pk; kk = kk < 1 ? 1 : (kk > E ? E : kk);
    epilogue(acc, valid, token, kk, out, N, sh_psum, sh_cnt, &sh_ent,
             tid, lane, gridDim.x);
}

// ===========================================================================
// Host (no statics; deterministic per call)
// ===========================================================================
typedef CUresult (*EncodeTiledFn)(
    CUtensorMap*, CUtensorMapDataType, cuuint32_t, void*,
    const cuuint64_t*, const cuuint64_t*, const cuuint32_t*, const cuuint32_t*,
    CUtensorMapInterleave, CUtensorMapSwizzle, CUtensorMapL2promotion,
    CUtensorMapFloatOOBfill);

extern "C" void kernel_launch(void* const* d_in, const int* in_sizes, int n_in,
                              void* d_out, int out_size) {
    const float* x = (const float*)d_in[0];
    const float* W = (const float*)d_in[1];
    const int*  pk = (const int*)d_in[2];
    int N = in_sizes[0] / DDIM;
    float* out = (float*)d_out;

    int grid = GRID;
    int tok_per_blk = (N + grid - 1) / grid;
    bool shape_ok = tok_per_blk <= ROWS;
    if (!shape_ok) {
        grid = (N + TPB_C - 1) / TPB_C;
        tok_per_blk = TPB_C;
    }

    EncodeTiledFn enc = nullptr;
    {
        void* p = nullptr;
#if CUDART_VERSION >= 12050
        cudaDriverEntryPointQueryResult st;
        if (cudaGetDriverEntryPointByVersion("cuTensorMapEncodeTiled", &p, 12000,
                                             cudaEnableDefault, &st) == cudaSuccess &&
            st == cudaDriverEntryPointSuccess)
            enc = (EncodeTiledFn)p;
#else
        if (cudaGetDriverEntryPoint("cuTensorMapEncodeTiled", &p,
                                    cudaEnableDefault) == cudaSuccess)
            enc = (EncodeTiledFn)p;
#endif
    }

    bool use_tma = false;
    CUtensorMap tmap;
    if (shape_ok && enc) {
        cuuint64_t dims[2]    = {(cuuint64_t)DDIM, (cuuint64_t)N};
        cuuint64_t strides[1] = {(cuuint64_t)DDIM * sizeof(float)};
        cuuint32_t box[2]     = {CF_T, ROWS};
        cuuint32_t estr[2]    = {1, 1};
        if (enc(&tmap, CU_TENSOR_MAP_DATA_TYPE_FLOAT32, 2, (void*)x,
                dims, strides, box, estr,
                CU_TENSOR_MAP_INTERLEAVE_NONE, CU_TENSOR_MAP_SWIZZLE_128B,
                CU_TENSOR_MAP_L2_PROMOTION_L2_128B,
                CU_TENSOR_MAP_FLOAT_OOB_FILL_NONE) == CUDA_SUCCESS)
            use_tma = true;
    }

    if (use_tma) {
        cudaFuncSetAttribute(router_tma,
                             cudaFuncAttributeMaxDynamicSharedMemorySize, SMEM_T);
        router_tma<<<grid, TPB_T, SMEM_T>>>(tmap, W, pk, out, N, tok_per_blk);
    } else {
        cudaFuncSetAttribute(router_cp,
                             cudaFuncAttributeMaxDynamicSharedMemorySize, SMEM_C);
        router_cp<<<grid, TPB_C, SMEM_C>>>(x, W, pk, out, N, tok_per_blk);
    }
}